// round 9
// baseline (speedup 1.0000x reference)
#include <cuda_runtime.h>
#include <cuda_bf16.h>

// PMF: out[p] = relu(dot(user_emb[user_ids[p]], item_emb[item_ids[p]])), D=64 fp32.
//
// R9: cp.async pipelined gather. R4 and R7b both ran 90.6us with ~50% load
// duty (serial id->row exposure per warp). Here each CTA loops over 8 tiles
// with a 3-buffer smem stage and wait_group 2:
//   iter t: issue rows(t+2) via cp.async (ids prefetched at iter t-2),
//           commit, wait_group 2 (rows(t) landed), consume tile t.
// Two tiles per warp permanently in flight -> ~90% duty. No __syncthreads:
// each thread consumes only its own staged 16B chunks.
// 16 lanes per pair, 2 coalesced 128B lines per 256B row. PB=2 pairs/group.

#define HIDDEN 64
#define THREADS 256
#define GROUPS 16                         // 16-lane groups per CTA
#define PB 2                              // pairs per group per tile
#define TILE_PAIRS (GROUPS * PB)          // 32
#define T_TILES 8
#define PAIRS_PER_BLOCK (TILE_PAIRS * T_TILES)  // 256
#define NBUF 3

__device__ __forceinline__ void cp_async16(unsigned int smem_addr, const void* gptr) {
    asm volatile("cp.async.cg.shared.global [%0], [%1], 16;\n"
                 :: "r"(smem_addr), "l"(gptr));
}

__global__ __launch_bounds__(THREADS)
void pmf_kernel(const float* __restrict__ user_emb,
                const float* __restrict__ item_emb,
                const int*   __restrict__ user_ids,
                const int*   __restrict__ item_ids,
                float*       __restrict__ out,
                int num_pairs)
{
    // 3 buffers x 2 tables x PB x 256 threads x 16B = 48KB (static smem limit)
    __shared__ float4 stage[NBUF][2][PB][THREADS];

    const int tid   = threadIdx.x;
    const int group = tid >> 4;
    const int lane  = tid & 15;
    const int cta_base = blockIdx.x * PAIRS_PER_BLOCK;

    int uid[2][PB], iid[2][PB];   // id slots, ping-pong (slot = tile & 1)

    auto load_ids = [&](int tt, int s) {
        #pragma unroll
        for (int k = 0; k < PB; k++) {
            int p = cta_base + tt * TILE_PAIRS + group * PB + k;
            int q = (tt < T_TILES && p < num_pairs) ? p : 0;
            uid[s][k] = __ldg(&user_ids[q]);
            iid[s][k] = __ldg(&item_ids[q]);
        }
    };

    auto issue_rows = [&](int tt, int s) {
        if (tt < T_TILES) {
            unsigned int b = (unsigned int)(tt % NBUF);
            unsigned int su = (unsigned int)__cvta_generic_to_shared(&stage[b][0][0][tid]);
            unsigned int sv = (unsigned int)__cvta_generic_to_shared(&stage[b][1][0][tid]);
            #pragma unroll
            for (int k = 0; k < PB; k++) {
                const float4* ur = reinterpret_cast<const float4*>(
                    user_emb + (long long)uid[s][k] * HIDDEN) + lane;
                const float4* ir = reinterpret_cast<const float4*>(
                    item_emb + (long long)iid[s][k] * HIDDEN) + lane;
                cp_async16(su + k * (THREADS * 16), ur);
                cp_async16(sv + k * (THREADS * 16), ir);
            }
        }
        asm volatile("cp.async.commit_group;\n" ::: "memory");
    };

    // Prologue: ids for tiles 0,1; rows for tiles 0,1; ids for tiles 2,3.
    load_ids(0, 0);
    load_ids(1, 1);
    issue_rows(0, 0);
    load_ids(2, 0);
    issue_rows(1, 1);
    load_ids(3, 1);

    #pragma unroll
    for (int t = 0; t < T_TILES; t++) {
        // Issue tile t+2 (ids already resident in slot t&1), then prefetch
        // ids for tile t+4 into the freed slot.
        issue_rows(t + 2, t & 1);
        load_ids(t + 4, t & 1);

        // Wait until tile t's group has landed (<=2 groups still pending).
        asm volatile("cp.async.wait_group 2;\n" ::: "memory");

        // Consume tile t: dot, 16-lane reduction, store.
        const int b = t % NBUF;
        #pragma unroll
        for (int k = 0; k < PB; k++) {
            float4 u = stage[b][0][k][tid];
            float4 v = stage[b][1][k][tid];
            float acc = u.x * v.x + u.y * v.y + u.z * v.z + u.w * v.w;
            acc += __shfl_xor_sync(0xFFFFFFFFu, acc, 8);
            acc += __shfl_xor_sync(0xFFFFFFFFu, acc, 4);
            acc += __shfl_xor_sync(0xFFFFFFFFu, acc, 2);
            acc += __shfl_xor_sync(0xFFFFFFFFu, acc, 1);
            int p = cta_base + t * TILE_PAIRS + group * PB + k;
            if (lane == 0 && p < num_pairs)
                out[p] = fmaxf(acc, 0.0f);
        }
    }
}

extern "C" void kernel_launch(void* const* d_in, const int* in_sizes, int n_in,
                              void* d_out, int out_size)
{
    const float* user_emb = (const float*)d_in[0];
    const float* item_emb = (const float*)d_in[1];
    const int*   user_ids = (const int*)d_in[2];
    const int*   item_ids = (const int*)d_in[3];
    float*       out      = (float*)d_out;

    int num_pairs = in_sizes[2];
    int blocks = (num_pairs + PAIRS_PER_BLOCK - 1) / PAIRS_PER_BLOCK;

    pmf_kernel<<<blocks, THREADS>>>(user_emb, item_emb, user_ids, item_ids,
                                    out, num_pairs);
}